// round 16
// baseline (speedup 1.0000x reference)
#include <cuda_runtime.h>

// ============================================================================
// CSNN (T=8, B=32), ONE kernel, barrier-free redundant interval zero-proof:
//   L1 can spike only if max|x| >= thresh_c = (vth1*0.999/8 - b1[c]) /
//   sum|w1[c,:]| (input broadcast over T => constant L1 drive), and bias-only
//   IF of L2..L5 fires nothing (FCs have no bias) => output exactly 0.
//   Hot path per block: coalesced w1 smem stage + MLP-8 x-scan (overlapped),
//   conflict-free smem row sums, 2 block barriers, NO inter-block comm.
//   Zero => block 0 writes out=0, all exit. Else grid-barrier fallback.
// Layout: [T][B][C][H][W] row-major, n = t*32 + b.
// ============================================================================

#define TSTEPS 8
#define BATCH  32
#define NBLK   64
#define NTHR   256

typedef unsigned char  u8;
typedef unsigned int   u32;

// ---------------- static scratch ----------------
__device__ u8    g_s1 [8*32*128*26*26];
__device__ u8    g_s2 [8*32*128*13*13];
__device__ u8    g_s3 [8*32*192*13*13];
__device__ u8    g_s4 [8*32*128*13*13];
__device__ u8    g_s5 [8*32*128*6*6];
__device__ float g_zf1[8*32*2048];
__device__ u8    g_sf1[8*32*2048];
__device__ float g_zf2[8*32*512];
__device__ u8    g_sf2[8*32*512];

__device__ u8 g_m1[32*8];
__device__ u8 g_m2[32*8];
__device__ u8 g_m3[32*12];
__device__ u8 g_m4[32*8];

#define NGZ 168
__device__ u32 g_gz[NGZ];

// grid barrier (fallback path only; generation counting, replay-safe)
__device__ u32 g_barcnt;
__device__ u32 g_bargen;

__device__ __forceinline__ void gsync()
{
    __threadfence();
    __syncthreads();
    if (threadIdx.x == 0) {
        u32 gen = *(volatile u32*)&g_bargen;
        if (atomicAdd(&g_barcnt, 1u) == NBLK - 1) {
            g_barcnt = 0;
            __threadfence();
            atomicAdd(&g_bargen, 1u);
        } else {
            while (*(volatile u32*)&g_bargen == gen) { }
        }
    }
    __syncthreads();
}

#define SMEM_BYTES 16896

// ---------------------------------------------------------------------------
__device__ __forceinline__ u32 if_bits_const(float a, float vth)
{
    if (a * 8.f < vth * 0.999f) return 0u;
    float v = 0.f; u32 bits = 0;
    #pragma unroll
    for (int t = 0; t < TSTEPS; t++) {
        v += a;
        float sp = (v >= vth) ? 1.f : 0.f;
        v -= v * sp;
        if (sp != 0.f) bits |= 1u << t;
    }
    return bits;
}

// ---------------------------------------------------------------------------
// conv1 (1ch,5x5,s1,p1) + IF for one (image b, 16-oc group g). Fallback only.
// ---------------------------------------------------------------------------
__device__ void conv1_item(char* smraw, int b, int g,
    const float* __restrict__ x, const float* __restrict__ w,
    const float* __restrict__ bias, u8* __restrict__ s1, u8* __restrict__ m1,
    float vth)
{
    float* sx    = (float*)smraw;
    float* sw    = sx + 900;
    u32*   sflag = (u32*)(sw + 16*28);
    u8*    smask = (u8*)(sflag + 16);
    const int tid = threadIdx.x;
    const int oc0 = g * 16;

    __syncthreads();
    #pragma unroll 1
    for (int i = tid; i < 900; i += NTHR) {
        int r = i / 30, c = i - 30*r;
        float v = 0.f;
        if (r >= 1 && r < 29 && c >= 1 && c < 29)
            v = x[b*784 + (r-1)*28 + (c-1)];
        sx[i] = v;
    }
    #pragma unroll 1
    for (int i = tid; i < 16*28; i += NTHR) {
        int oc = i / 28, k = i - oc*28;
        sw[i] = (k < 25) ? w[(oc0 + oc)*25 + k] : 0.f;
    }
    if (tid < 16) sflag[tid] = 0u;
    __syncthreads();

    float bv[16];
    #pragma unroll
    for (int oc = 0; oc < 16; oc++) bv[oc] = __ldg(&bias[oc0 + oc]);

    #pragma unroll 1
    for (int pos = tid; pos < 676; pos += NTHR) {
        int oy = pos / 26, ox = pos - 26*oy;
        float xv[28];
        #pragma unroll
        for (int ky = 0; ky < 5; ky++)
            #pragma unroll
            for (int kx = 0; kx < 5; kx++)
                xv[ky*5 + kx] = sx[(oy+ky)*30 + ox+kx];
        xv[25] = xv[26] = xv[27] = 0.f;
        #pragma unroll
        for (int oc = 0; oc < 16; oc++) {
            float a = bv[oc];
            #pragma unroll
            for (int q = 0; q < 7; q++) {
                float4 w4 = *reinterpret_cast<const float4*>(&sw[oc*28 + q*4]);
                a = fmaf(xv[q*4+0], w4.x, a);
                a = fmaf(xv[q*4+1], w4.y, a);
                a = fmaf(xv[q*4+2], w4.z, a);
                a = fmaf(xv[q*4+3], w4.w, a);
            }
            u32 bits = if_bits_const(a, vth);
            smask[pos*16 + oc] = (u8)bits;
            if (bits) atomicOr(&sflag[oc], bits);
        }
    }
    __syncthreads();

    u32 tany = 0;
    #pragma unroll
    for (int oc = 0; oc < 16; oc++) tany |= sflag[oc];
    if (tid == 0) m1[b*8 + g] = (u8)tany;

    if (tany) {
        #pragma unroll 1
        for (int t = 0; t < TSTEPS; t++) {
            if (!((tany >> t) & 1u)) continue;
            for (int i = tid; i < 16*676; i += NTHR) {
                int oc = i / 676, pos = i - oc*676;
                s1[((size_t)(t*BATCH + b)*128 + oc0 + oc)*676 + pos] =
                    (u8)((smask[pos*16 + oc] >> t) & 1u);
            }
        }
    }
}

// ---------------------------------------------------------------------------
// Fallback machinery (dense / partially-dense data only).
// ---------------------------------------------------------------------------
template <int CIN, int COUT, int IH, int IW, int OH, int OW,
          int KH, int KW, int S, int PAD, int CC, bool GATED>
__device__ void conv_item(char* smraw, int oc0, int b,
    const u8* __restrict__ in, const float* __restrict__ wgt,
    const float* __restrict__ bias, u8* __restrict__ sout,
    const u8* __restrict__ min_, u8* __restrict__ mout,
    u32* __restrict__ gany, float vth)
{
    constexpr int TC    = 16;
    constexpr int P     = OH * OW;
    constexpr int PIH   = (OH - 1) * S + KH;
    constexpr int PIW   = (OW - 1) * S + KW;
    constexpr int KK    = KH * KW;
    constexpr int KWPAD = (KK + 3) & ~3;
    constexpr int GIN   = CIN / 16;
    constexpr int GOUT  = COUT / 16;
    constexpr int MW    = GIN / 4;

    u32*   s_mw = (u32*)smraw;
    float* s_in = (float*)(smraw + 16);
    float* s_w  = s_in + CC*PIH*PIW;
    const u8* s_mb = (const u8*)s_mw;
    const int tid = threadIdx.x;

    __syncthreads();
    if (tid < MW) s_mw[tid] = ((const u32*)min_)[b*MW + tid];
    __syncthreads();

    u32 allb = 0;
    #pragma unroll
    for (int i = 0; i < MW; i++) allb |= s_mw[i];
    u32 tmask = (allb | (allb >> 8) | (allb >> 16) | (allb >> 24)) & 0xFFu;

    float bi[TC];
    #pragma unroll
    for (int i = 0; i < TC; i++) bi[i] = __ldg(&bias[oc0 + i]);

    if (tmask == 0u) {
        u32 spb[TC]; u32 tany = 0;
        #pragma unroll
        for (int oc = 0; oc < TC; oc++) {
            spb[oc] = if_bits_const(bi[oc], vth);
            tany |= spb[oc];
        }
        if (GATED) {
            if (tid == 0) mout[b*GOUT + (oc0 >> 4)] = (u8)tany;
            if (tany) {
                #pragma unroll 1
                for (int t = 0; t < TSTEPS; t++) {
                    if (!((tany >> t) & 1u)) continue;
                    for (int i = tid; i < TC*P; i += NTHR) {
                        int oc = i / P, p = i - oc*P;
                        sout[((size_t)(t*BATCH + b)*COUT + oc0 + oc)*P + p] =
                            (u8)((spb[oc] >> t) & 1u);
                    }
                }
            }
        } else {
            #pragma unroll 1
            for (int i = tid; i < TSTEPS*TC*P; i += NTHR) {
                int t   = i / (TC*P);
                int rem = i - t*(TC*P);
                int oc  = rem / P;
                int p   = rem - oc*P;
                sout[((size_t)(t*BATCH + b)*COUT + oc0 + oc)*P + p] =
                    (u8)((spb[oc] >> t) & 1u);
            }
            if (tany && tid == 0) gany[oc0 >> 4] = 1u;
        }
        return;
    }

    const int pos = tid;
    const bool active = pos < P;
    const int oy = pos / OW;
    const int ox = pos - oy * OW;

    float v[TC];
    #pragma unroll
    for (int i = 0; i < TC; i++) v[i] = 0.f;

    u32 tany_acc = 0;
    for (int t = 0; t < TSTEPS; t++) {
        float acc[TC];
        #pragma unroll
        for (int i = 0; i < TC; i++) acc[i] = 0.f;

        if ((tmask >> t) & 1u) {
            #pragma unroll 1
            for (int c0 = 0; c0 < CIN; c0 += CC) {
                if (!((s_mb[c0 >> 4] >> t) & 1u)) continue;

                #pragma unroll 1
                for (int i = tid; i < CC*PIH*PIW; i += NTHR) {
                    int cc = i / (PIH*PIW);
                    int pp = i - cc*(PIH*PIW);
                    int py = pp / PIW;
                    int px = pp - py*PIW;
                    int iy = py - PAD, ix = px - PAD;
                    float val = 0.f;
                    if (iy >= 0 && iy < IH && ix >= 0 && ix < IW)
                        val = (float)in[((size_t)(t*BATCH + b)*CIN + c0 + cc)*(IH*IW)
                                        + iy*IW + ix];
                    s_in[cc*(PIH*PIW) + pp] = val;
                }
                #pragma unroll 1
                for (int i = tid; i < CC*TC*KK; i += NTHR) {
                    int cc  = i / (TC*KK);
                    int rem = i - cc*(TC*KK);
                    int oc  = rem / KK;
                    int k   = rem - oc*KK;
                    s_w[(cc*TC + oc)*KWPAD + k] = wgt[((oc0 + oc)*CIN + c0 + cc)*KK + k];
                }
                __syncthreads();
                if (active) {
                    #pragma unroll
                    for (int cc = 0; cc < CC; cc++) {
                        float xin[KK];
                        #pragma unroll
                        for (int ky = 0; ky < KH; ky++)
                            #pragma unroll
                            for (int kx = 0; kx < KW; kx++)
                                xin[ky*KW + kx] =
                                    s_in[cc*(PIH*PIW) + (oy*S + ky)*PIW + ox*S + kx];
                        #pragma unroll
                        for (int oc = 0; oc < TC; oc++) {
                            float wv[KWPAD];
                            #pragma unroll
                            for (int q = 0; q < KWPAD/4; q++) {
                                float4 v4 = *reinterpret_cast<const float4*>(
                                    &s_w[(cc*TC + oc)*KWPAD + q*4]);
                                wv[q*4+0] = v4.x; wv[q*4+1] = v4.y;
                                wv[q*4+2] = v4.z; wv[q*4+3] = v4.w;
                            }
                            float a = acc[oc];
                            #pragma unroll
                            for (int k = 0; k < KK; k++)
                                a = fmaf(xin[k], wv[k], a);
                            acc[oc] = a;
                        }
                    }
                }
                __syncthreads();
            }
        }

        u32 myspk = 0;
        if (active) {
            #pragma unroll
            for (int oc = 0; oc < TC; oc++) {
                v[oc] += acc[oc] + bi[oc];
                float sp = (v[oc] >= vth) ? 1.f : 0.f;
                v[oc] -= v[oc] * sp;
                if (sp != 0.f) myspk |= 1u << oc;
            }
        }
        u32 bm = (u32)__syncthreads_or((int)myspk);

        if (GATED) {
            if (bm) {
                tany_acc |= 1u << t;
                if (active) {
                    #pragma unroll
                    for (int oc = 0; oc < TC; oc++)
                        sout[((size_t)(t*BATCH + b)*COUT + oc0 + oc)*P + pos] =
                            (u8)((myspk >> oc) & 1u);
                }
            }
        } else {
            if (active) {
                #pragma unroll
                for (int oc = 0; oc < TC; oc++)
                    sout[((size_t)(t*BATCH + b)*COUT + oc0 + oc)*P + pos] =
                        (u8)((myspk >> oc) & 1u);
            }
            if (bm && tid == 0) gany[oc0 >> 4] = 1u;
        }
    }
    if (GATED && tid == 0) mout[b*GOUT + (oc0 >> 4)] = (u8)tany_acc;
}

__device__ void gemm_stage(char* smraw,
    const u8* __restrict__ A, const float* __restrict__ B,
    float* __restrict__ C, int M, int N, int K,
    const u32* __restrict__ gany, int ppc, int ngrp)
{
    float* As    = (float*)smraw;
    float* Bs    = As + 16*64;
    u32*   s_any = (u32*)(Bs + 16*64);
    const int tid = threadIdx.x;

    __syncthreads();
    u32 part = 0;
    #pragma unroll 1
    for (int i = tid; i < ngrp; i += NTHR) {
        u32 g = __ldg(&gany[i]);
        s_any[i] = g;
        part |= g;
    }
    u32 anyall = (u32)__syncthreads_or((int)part);
    if (!anyall) return;

    const int tm = tid >> 4, tn = tid & 15;
    const int r = tid >> 2, q = (tid & 3) << 2;
    const int ntx = N / 64;
    const int ntiles = ntx * (M / 64);

    for (int tile = blockIdx.x; tile < ntiles; tile += NBLK) {
        int n0 = (tile % ntx) * 64;
        int m0 = (tile / ntx) * 64;

        float c[4][4];
        #pragma unroll
        for (int i = 0; i < 4; i++)
            #pragma unroll
            for (int j = 0; j < 4; j++) c[i][j] = 0.f;

        for (int k0 = 0; k0 < K; k0 += 16) {
            int g1 = (k0 / ppc) >> 4;
            int g2 = ((k0 + 15) / ppc) >> 4;
            if (!(s_any[g1] | s_any[g2])) continue;

            uchar4 av = *reinterpret_cast<const uchar4*>(&A[(m0 + r) * K + k0 + q]);
            As[(q+0)*64 + r] = (float)av.x; As[(q+1)*64 + r] = (float)av.y;
            As[(q+2)*64 + r] = (float)av.z; As[(q+3)*64 + r] = (float)av.w;
            int f = av.x | av.y | av.z | av.w;
            if (__syncthreads_or(f)) {
                float4 bv = *reinterpret_cast<const float4*>(&B[(n0 + r) * K + k0 + q]);
                Bs[(q+0)*64 + r] = bv.x; Bs[(q+1)*64 + r] = bv.y;
                Bs[(q+2)*64 + r] = bv.z; Bs[(q+3)*64 + r] = bv.w;
                __syncthreads();
                #pragma unroll
                for (int kk = 0; kk < 16; kk++) {
                    float4 a = *reinterpret_cast<const float4*>(&As[kk*64 + tm*4]);
                    float4 b = *reinterpret_cast<const float4*>(&Bs[kk*64 + tn*4]);
                    c[0][0] = fmaf(a.x, b.x, c[0][0]); c[0][1] = fmaf(a.x, b.y, c[0][1]);
                    c[0][2] = fmaf(a.x, b.z, c[0][2]); c[0][3] = fmaf(a.x, b.w, c[0][3]);
                    c[1][0] = fmaf(a.y, b.x, c[1][0]); c[1][1] = fmaf(a.y, b.y, c[1][1]);
                    c[1][2] = fmaf(a.y, b.z, c[1][2]); c[1][3] = fmaf(a.y, b.w, c[1][3]);
                    c[2][0] = fmaf(a.z, b.x, c[2][0]); c[2][1] = fmaf(a.z, b.y, c[2][1]);
                    c[2][2] = fmaf(a.z, b.z, c[2][2]); c[2][3] = fmaf(a.z, b.w, c[2][3]);
                    c[3][0] = fmaf(a.w, b.x, c[3][0]); c[3][1] = fmaf(a.w, b.y, c[3][1]);
                    c[3][2] = fmaf(a.w, b.z, c[3][2]); c[3][3] = fmaf(a.w, b.w, c[3][3]);
                }
                __syncthreads();
            }
        }
        #pragma unroll
        for (int i = 0; i < 4; i++)
            #pragma unroll
            for (int j = 0; j < 4; j++)
                C[(m0 + tm*4 + i) * N + n0 + tn*4 + j] = c[i][j];
    }
}

__device__ void if_stage(const float* __restrict__ z, u8* __restrict__ s,
                         int E, int F,
                         const u32* __restrict__ gin, int ngin,
                         u32* __restrict__ gout, float vth)
{
    u32 part = 0;
    #pragma unroll 1
    for (int i = threadIdx.x; i < ngin; i += NTHR)
        part |= __ldg(&gin[i]);
    u32 anyall = (u32)__syncthreads_or((int)part);
    if (!anyall) return;

    for (int e = blockIdx.x * NTHR + threadIdx.x; e < E; e += NBLK * NTHR) {
        float v = 0.f;
        u32 any = 0;
        #pragma unroll
        for (int t = 0; t < TSTEPS; t++) {
            v += z[t*E + e];
            float sp = (v >= vth) ? 1.f : 0.f;
            v -= v * sp;
            s[t*E + e] = (u8)sp;
            any |= (sp != 0.f);
        }
        if (any) gout[(e % F) >> 4] = 1u;
    }
}

__device__ void fc3_stage(const u8* __restrict__ A, const float* __restrict__ W,
                          float* __restrict__ out, const u32* __restrict__ gany,
                          float vth)
{
    int idx = blockIdx.x * NTHR + threadIdx.x;
    if (idx >= 320) return;
    int cls = idx % 10, b = idx / 10;

    u32 anyall = 0;
    #pragma unroll
    for (int i = 0; i < 32; i++) anyall |= __ldg(&gany[i]);

    float m = 0.f;
    if (anyall) {
        const float* wr = W + cls * 512;
        float v = 0.f;
        #pragma unroll 1
        for (int t = 0; t < TSTEPS; t++) {
            const u8* ar = A + (t*BATCH + b) * 512;
            float d = 0.f;
            #pragma unroll 4
            for (int k = 0; k < 512; k += 4) {
                uchar4 av = *reinterpret_cast<const uchar4*>(ar + k);
                float4 wv = *reinterpret_cast<const float4*>(wr + k);
                d = fmaf((float)av.x, wv.x, d); d = fmaf((float)av.y, wv.y, d);
                d = fmaf((float)av.z, wv.z, d); d = fmaf((float)av.w, wv.w, d);
            }
            v += d;
            float sp = (v >= vth) ? 1.f : 0.f;
            v -= v * sp;
            m += sp;
        }
    }
    out[b*10 + cls] = m * (1.f / TSTEPS);
}

// ---------------------------------------------------------------------------
// THE kernel: barrier-free redundant zero-proof; fallback pipeline if needed.
// ---------------------------------------------------------------------------
__global__ __launch_bounds__(NTHR, 2) void snn_one(
    const float* __restrict__ x,
    const float* __restrict__ w1, const float* __restrict__ b1,
    const float* __restrict__ w2, const float* __restrict__ b2,
    const float* __restrict__ w3, const float* __restrict__ b3,
    const float* __restrict__ w4, const float* __restrict__ b4,
    const float* __restrict__ w5, const float* __restrict__ b5,
    const float* __restrict__ fc1w, const float* __restrict__ fc2w,
    const float* __restrict__ fc3w, float* __restrict__ out)
{
    __shared__ __align__(16) char sm[SMEM_BYTES];
    const int bid = blockIdx.x;
    const int tid = threadIdx.x;

    float* sw1 = (float*)sm;          // 3200 floats (w1 staged, coalesced)
    float* pm  = sw1 + 3200;          // 8 warp partials

    // ---- coalesced w1 stage into smem (800 float4, 3-4 per thread) ----
    {
        const float4* w14 = reinterpret_cast<const float4*>(w1);
        #pragma unroll
        for (int i = tid; i < 800; i += NTHR)
            reinterpret_cast<float4*>(sw1)[i] = __ldg(w14 + i);
    }

    // ---- bias-IF proof bits (independent, overlap with x-scan) ----
    float b1v = 0.f;
    u32 part = 0;
    if (tid < 128) {
        b1v = __ldg(&b1[tid]);
        part |= if_bits_const(__ldg(&b2[tid]),  71.f);
        part |= if_bits_const(__ldg(&b4[tid]), 144.f);
        part |= if_bits_const(__ldg(&b5[tid]),  79.f);
    }
    if (tid < 192) part |= if_bits_const(__ldg(&b3[tid]), 93.f);

    // ---- max|x| over 6272 float4 with explicit MLP=8 ----
    const float4* x4 = reinterpret_cast<const float4*>(x);
    float mx = 0.f;
    #pragma unroll 1
    for (int i = tid; i < 6144; i += NTHR * 8) {
        float4 r0 = __ldg(x4 + i);
        float4 r1 = __ldg(x4 + i + NTHR);
        float4 r2 = __ldg(x4 + i + NTHR*2);
        float4 r3 = __ldg(x4 + i + NTHR*3);
        float4 r4 = __ldg(x4 + i + NTHR*4);
        float4 r5 = __ldg(x4 + i + NTHR*5);
        float4 r6 = __ldg(x4 + i + NTHR*6);
        float4 r7 = __ldg(x4 + i + NTHR*7);
        float m0 = fmaxf(fmaxf(fabsf(r0.x), fabsf(r0.y)), fmaxf(fabsf(r0.z), fabsf(r0.w)));
        float m1 = fmaxf(fmaxf(fabsf(r1.x), fabsf(r1.y)), fmaxf(fabsf(r1.z), fabsf(r1.w)));
        float m2 = fmaxf(fmaxf(fabsf(r2.x), fabsf(r2.y)), fmaxf(fabsf(r2.z), fabsf(r2.w)));
        float m3 = fmaxf(fmaxf(fabsf(r3.x), fabsf(r3.y)), fmaxf(fabsf(r3.z), fabsf(r3.w)));
        float m4 = fmaxf(fmaxf(fabsf(r4.x), fabsf(r4.y)), fmaxf(fabsf(r4.z), fabsf(r4.w)));
        float m5 = fmaxf(fmaxf(fabsf(r5.x), fabsf(r5.y)), fmaxf(fabsf(r5.z), fabsf(r5.w)));
        float m6 = fmaxf(fmaxf(fabsf(r6.x), fabsf(r6.y)), fmaxf(fabsf(r6.z), fabsf(r6.w)));
        float m7 = fmaxf(fmaxf(fabsf(r7.x), fabsf(r7.y)), fmaxf(fabsf(r7.z), fabsf(r7.w)));
        mx = fmaxf(mx, fmaxf(fmaxf(fmaxf(m0, m1), fmaxf(m2, m3)),
                             fmaxf(fmaxf(m4, m5), fmaxf(m6, m7))));
    }
    if (tid < 128) {   // tail: 6272 - 6144 = 128 float4
        float4 a = __ldg(x4 + 6144 + tid);
        mx = fmaxf(mx, fmaxf(fmaxf(fabsf(a.x), fabsf(a.y)),
                             fmaxf(fabsf(a.z), fabsf(a.w))));
    }

    // ---- warp-shuffle reduce; ONE barrier publishes pm AND sw1 ----
    #pragma unroll
    for (int off = 16; off > 0; off >>= 1)
        mx = fmaxf(mx, __shfl_xor_sync(0xFFFFFFFFu, mx, off));
    if ((tid & 31) == 0) pm[tid >> 5] = mx;
    __syncthreads();
    float amax = pm[0];
    #pragma unroll
    for (int wd = 1; wd < NTHR/32; wd++) amax = fmaxf(amax, pm[wd]);

    // ---- L1 interval bound from smem-staged w1 (conflict-free LDS) ----
    if (tid < 128) {
        float ssum = 0.f;
        const float* wr = sw1 + tid * 25;
        #pragma unroll
        for (int k = 0; k < 25; k++) ssum += fabsf(wr[k]);
        float ahi = b1v + ssum * amax;   // upper bound on constant L1 drive
        if (ahi * 8.f >= 13515.f * 0.999f) part |= 1u;
    }
    u32 anyall = (u32)__syncthreads_or((int)part);

    if (!anyall) {
        // network provably zero end-to-end; no conv needed at all
        if (bid == 0)
            for (int i = tid; i < 320; i += NTHR) out[i] = 0.f;
        return;
    }

    // ================= FALLBACK: full pipeline =================
    if (bid == 0 && tid < NGZ) g_gz[tid] = 0u;   // published by first gsync
    u32* gany5  = g_gz + 0;
    u32* ganyf1 = g_gz + 8;
    u32* ganyf2 = g_gz + 136;

    for (int it = bid; it < 256; it += NBLK)
        conv1_item(sm, it >> 3, it & 7, x, w1, b1, g_s1, g_m1, 13515.f);
    gsync();

    for (int it = bid; it < 256; it += NBLK)
        conv_item<128,128,26,26,13,13,4,4,2,1,4,true>
            (sm, (it & 7) * 16, it >> 3, g_s1, w2, b2, g_s2, g_m1, g_m2,
             nullptr, 71.f);
    gsync();

    for (int it = bid; it < 384; it += NBLK)
        conv_item<128,192,13,13,13,13,3,3,1,1,8,true>
            (sm, (it % 12) * 16, it / 12, g_s2, w3, b3, g_s3, g_m2, g_m3,
             nullptr, 93.f);
    gsync();

    for (int it = bid; it < 256; it += NBLK)
        conv_item<192,128,13,13,13,13,3,3,1,1,8,true>
            (sm, (it & 7) * 16, it >> 3, g_s3, w4, b4, g_s4, g_m3, g_m4,
             nullptr, 144.f);
    gsync();

    for (int it = bid; it < 256; it += NBLK)
        conv_item<128,128,13,13,6,6,3,3,2,0,4,false>
            (sm, (it & 7) * 16, it >> 3, g_s4, w5, b5, g_s5, g_m4, nullptr,
             gany5, 79.f);
    gsync();

    gemm_stage(sm, g_s5, fc1w, g_zf1, 256, 2048, 4608, gany5, 36, 8);
    gsync();

    if_stage(g_zf1, g_sf1, 32*2048, 2048, gany5, 8, ganyf1, 2475.f);
    gsync();

    gemm_stage(sm, g_sf1, fc2w, g_zf2, 256, 512, 2048, ganyf1, 1, 128);
    gsync();

    if_stage(g_zf2, g_sf2, 32*512, 512, ganyf1, 128, ganyf2, 1357.f);
    gsync();

    fc3_stage(g_sf2, fc3w, out, ganyf2, 388.f);
}

// ---------------------------------------------------------------------------
extern "C" void kernel_launch(void* const* d_in, const int* in_sizes, int n_in,
                              void* d_out, int out_size)
{
    (void)in_sizes; (void)n_in; (void)out_size;
    snn_one<<<NBLK, NTHR>>>(
        (const float*)d_in[0],
        (const float*)d_in[1],  (const float*)d_in[2],
        (const float*)d_in[3],  (const float*)d_in[4],
        (const float*)d_in[5],  (const float*)d_in[6],
        (const float*)d_in[7],  (const float*)d_in[8],
        (const float*)d_in[9],  (const float*)d_in[10],
        (const float*)d_in[11], (const float*)d_in[12],
        (const float*)d_in[13], (float*)d_out);
}